// round 4
// baseline (speedup 1.0000x reference)
#include <cuda_runtime.h>

#define BATCH 32
#define SEQ   2048
#define NTHR  1024

// Scratch (allocation-free: __device__ globals)
__device__ float g_union[BATCH];
__device__ float g_intersect[BATCH];
__device__ float g_dmz2[BATCH];
__device__ float g_di2[BATCH];
__device__ float g_spmz[BATCH];
__device__ float g_spint[BATCH];
__device__ float g_maxmz[BATCH];
__device__ float g_maxint[BATCH];
__device__ int   g_counter = 0;   // reset by last block each run (graph-replay safe)

__device__ __forceinline__ float warpSum(float v) {
    #pragma unroll
    for (int o = 16; o; o >>= 1) v += __shfl_down_sync(0xffffffffu, v, o);
    return v;
}
__device__ __forceinline__ float warpMax(float v) {
    #pragma unroll
    for (int o = 16; o; o >>= 1) v = fmaxf(v, __shfl_down_sync(0xffffffffu, v, o));
    return v;
}

// ---- Fused kernel: stats + bitonic sort + nearest-neighbor search + finalize ----
__global__ __launch_bounds__(NTHR) void kMain(const float* __restrict__ pred_mz,
                                              const float* __restrict__ mz,
                                              const float* __restrict__ intensity,
                                              const float* __restrict__ pred_intensity,
                                              float* __restrict__ out) {
    __shared__ float s[SEQ];
    __shared__ float red7[7][32];
    __shared__ int   lastFlag;
    const int b    = blockIdx.x;
    const int t    = threadIdx.x;
    const int lane = t & 31;
    const int wrp  = t >> 5;
    const float* pm = pred_mz        + b * SEQ;
    const float* tm = mz             + b * SEQ;
    const float* ti = intensity      + b * SEQ;
    const float* pi = pred_intensity + b * SEQ;

    float cnt = 0.f, dmz2 = 0.f, di2 = 0.f, spmz = 0.f, spint = 0.f;
    float mxm = 0.f, mxi = 0.f;
    float a_reg[SEQ / NTHR], y_reg[SEQ / NTHR];   // pred values kept in regs for phase 2

    #pragma unroll
    for (int r = 0; r < SEQ / NTHR; r++) {
        int i = t + r * NTHR;
        float a = pm[i], c = tm[i], x = ti[i], y = pi[i];
        a_reg[r] = a; y_reg[r] = y;
        cnt  += (a >= 0.f ? 1.f : 0.f) + (c >= 0.f ? 1.f : 0.f);
        float d1 = a - c; dmz2 += d1 * d1;
        float d2 = y - x; di2  += d2 * d2;
        float sa = (float)((a > 0.f) - (a < 0.f));
        float sc = (float)((c > 0.f) - (c < 0.f));
        float sx = (float)((x > 0.f) - (x < 0.f));
        float sy = (float)((y > 0.f) - (y < 0.f));
        spmz  += fabsf(sa - sc);
        spint += fabsf(sy - sx);
        mxm = fmaxf(mxm, fabsf(c));
        mxi = fmaxf(mxi, fabsf(x));
        s[i] = (c >= 0.f) ? c : 0.f;   // masked mz (masked -> 0.0, as in reference)
    }

    // Batched stat reduction: 1 barrier instead of 21.
    cnt  = warpSum(cnt);  dmz2 = warpSum(dmz2); di2 = warpSum(di2);
    spmz = warpSum(spmz); spint = warpSum(spint);
    mxm  = warpMax(mxm);  mxi = warpMax(mxi);
    if (lane == 0) {
        red7[0][wrp] = cnt;  red7[1][wrp] = dmz2; red7[2][wrp] = di2;
        red7[3][wrp] = spmz; red7[4][wrp] = spint;
        red7[5][wrp] = mxm;  red7[6][wrp] = mxi;
    }
    __syncthreads();
    if (wrp < 7) {
        float v = red7[wrp][lane];
        if (wrp < 5) v = warpSum(v); else v = warpMax(v);
        if (lane == 0) {
            switch (wrp) {
                case 0: g_union[b]  = v; break;
                case 1: g_dmz2[b]   = v; break;
                case 2: g_di2[b]    = v; break;
                case 3: g_spmz[b]   = v; break;
                case 4: g_spint[b]  = v; break;
                case 5: g_maxmz[b]  = v; break;
                case 6: g_maxint[b] = v; break;
            }
        }
    }

    // Bitonic sort of s[0..2047] ascending.
    // For j <= 16 both exchange partners (i, i^j) live in the same 32-element
    // block owned by one warp (thread t owns s[t] and s[1024+t]; partner thread
    // t^j is in the same warp for j < 32) -> __syncwarp suffices. A full block
    // barrier is needed only when the PREVIOUS pass wrote cross-warp, which is
    // covered conservatively by j >= 16.
    for (int k = 2; k <= SEQ; k <<= 1) {
        for (int j = k >> 1; j > 0; j >>= 1) {
            if (j >= 16) __syncthreads(); else __syncwarp();
            #pragma unroll
            for (int r = 0; r < SEQ / NTHR; r++) {
                int i   = t + r * NTHR;
                int ixj = i ^ j;
                if (ixj > i) {
                    float a  = s[i];
                    float bb = s[ixj];
                    bool asc = ((i & k) == 0);
                    if ((a > bb) == asc) { s[i] = bb; s[ixj] = a; }
                }
            }
        }
    }
    __syncthreads();

    // Nearest-neighbor soft intersect: max_j exp(-|a - mz_j|/T) = exp(-min_dist/T)
    float acc = 0.f;
    #pragma unroll
    for (int r = 0; r < SEQ / NTHR; r++) {
        float a = a_reg[r];
        if (a >= 0.f) {
            // Branchless lower bound; pos saturates at SEQ-1. fabsf on both
            // bracket candidates keeps the true nearest in the candidate set.
            int pos = 0;
            #pragma unroll
            for (int st = SEQ / 2; st > 0; st >>= 1) {
                int np = pos + st;            // np <= SEQ-1 always
                if (s[np - 1] < a) pos = np;
            }
            float d = fabsf(a - s[pos]);
            if (pos > 0) d = fminf(d, fabsf(a - s[pos - 1]));
            acc += __expf(-10.0f * d) * y_reg[r];
        }
    }
    acc = warpSum(acc);
    if (lane == 0) red7[0][wrp] = acc;
    __syncthreads();
    float v = 0.f;
    if (wrp == 0) v = warpSum(red7[0][lane]);

    // ---- last-block finalize ----
    if (t == 0) {
        g_intersect[b] = v;
        __threadfence();
        int prev = atomicAdd(&g_counter, 1);
        lastFlag = (prev == BATCH - 1) ? 1 : 0;
    }
    __syncthreads();
    if (lastFlag) {
        __threadfence();
        if (t < 32) {
            const float EPS = 1e-8f;
            float sj     = 1.f - (g_intersect[t] + EPS) / (g_union[t] + EPS);
            float dmz2b  = g_dmz2[t];
            float di2b   = g_di2[t];
            float spmzb  = g_spmz[t];
            float spintb = g_spint[t];
            float mxmb   = g_maxmz[t];
            float mxib   = g_maxint[t];
            #pragma unroll
            for (int o = 16; o; o >>= 1) {
                sj     += __shfl_down_sync(0xffffffffu, sj,     o);
                dmz2b  += __shfl_down_sync(0xffffffffu, dmz2b,  o);
                di2b   += __shfl_down_sync(0xffffffffu, di2b,   o);
                spmzb  += __shfl_down_sync(0xffffffffu, spmzb,  o);
                spintb += __shfl_down_sync(0xffffffffu, spintb, o);
                mxmb = fmaxf(mxmb, __shfl_down_sync(0xffffffffu, mxmb, o));
                mxib = fmaxf(mxib, __shfl_down_sync(0xffffffffu, mxib, o));
            }
            if (t == 0) {
                const float N = (float)(BATCH * SEQ);
                out[0] = sj / (float)BATCH;               // soft jaccard loss
                out[1] = (dmz2b / N) / (mxmb * mxmb);     // mse mz (normalized)
                out[2] = (di2b  / N) / (mxib * mxib);     // mse intensity (normalized)
                out[3] = (spmzb / N + spintb / N) * 0.5f; // sign penalty
                g_counter = 0;                            // reset for next graph replay
            }
        }
    }
}

extern "C" void kernel_launch(void* const* d_in, const int* in_sizes, int n_in,
                              void* d_out, int out_size) {
    const float* pred_mz        = (const float*)d_in[0];
    const float* mz             = (const float*)d_in[1];
    const float* intensity      = (const float*)d_in[2];
    const float* pred_intensity = (const float*)d_in[3];
    float* out = (float*)d_out;

    kMain<<<BATCH, NTHR>>>(pred_mz, mz, intensity, pred_intensity, out);
}

// round 8
// speedup vs baseline: 1.7975x; 1.7975x over previous
#include <cuda_runtime.h>

#define BATCH  32
#define SEQ    2048
#define CHUNK  512
#define NCHUNK 4                  // SEQ / CHUNK
#define NBLK   (BATCH * NCHUNK)   // 128
#define NTHR   256

// ---- scratch (allocation-free: __device__ globals; all rewritten every run) ----
__device__ float g_sorted[BATCH * SEQ];
__device__ float g_pcnt[NBLK], g_pdmz[NBLK], g_pdi[NBLK], g_pspm[NBLK],
                 g_pspi[NBLK], g_pmxm[NBLK], g_pmxi[NBLK], g_pint[NBLK];

__device__ __forceinline__ int SK(int i) { return i + (i >> 5); }  // bank-skew index
#define REG   528                 // skewed size of one 512-chunk region
#define SKSZ  (NCHUNK * REG)      // 2112 floats

__device__ __forceinline__ float warpSum(float v) {
    #pragma unroll
    for (int o = 16; o; o >>= 1) v += __shfl_down_sync(0xffffffffu, v, o);
    return v;
}
__device__ __forceinline__ float warpMax(float v) {
    #pragma unroll
    for (int o = 16; o; o >>= 1) v = fmaxf(v, __shfl_down_sync(0xffffffffu, v, o));
    return v;
}

// ================= Kernel 1: stats partials + per-chunk bitonic sort =================
__global__ __launch_bounds__(NTHR) void kSort(const float* __restrict__ pred_mz,
                                              const float* __restrict__ mz,
                                              const float* __restrict__ intensity,
                                              const float* __restrict__ pred_intensity) {
    __shared__ float s[REG];        // one skewed 512-chunk
    __shared__ float red7[7][8];
    const int t    = threadIdx.x;
    const int lane = t & 31;
    const int w    = t >> 5;
    const int blk  = blockIdx.x;
    const int segBase = blk * CHUNK;       // blk = b*4 + c; contiguous global segment

    const float2 a2 = ((const float2*)pred_mz)       [segBase / 2 + t];
    const float2 c2 = ((const float2*)mz)            [segBase / 2 + t];
    const float2 x2 = ((const float2*)intensity)     [segBase / 2 + t];
    const float2 y2 = ((const float2*)pred_intensity)[segBase / 2 + t];

    float cnt = 0.f, dmz2 = 0.f, di2 = 0.f, spmz = 0.f, spint = 0.f, mxm = 0.f, mxi = 0.f;
    {
        float av[2] = {a2.x, a2.y}, cv[2] = {c2.x, c2.y};
        float xv[2] = {x2.x, x2.y}, yv[2] = {y2.x, y2.y};
        #pragma unroll
        for (int r = 0; r < 2; r++) {
            float a = av[r], cc = cv[r], x = xv[r], y = yv[r];
            cnt += (a >= 0.f ? 1.f : 0.f) + (cc >= 0.f ? 1.f : 0.f);
            float d1 = a - cc; dmz2 += d1 * d1;
            float d2 = y - x;  di2  += d2 * d2;
            float sa = (float)((a  > 0.f) - (a  < 0.f));
            float sc = (float)((cc > 0.f) - (cc < 0.f));
            float sx = (float)((x  > 0.f) - (x  < 0.f));
            float sy = (float)((y  > 0.f) - (y  < 0.f));
            spmz  += fabsf(sa - sc);
            spint += fabsf(sy - sx);
            mxm = fmaxf(mxm, fabsf(cc));
            mxi = fmaxf(mxi, fabsf(x));
        }
    }
    {   // masked mz into skewed smem (adjacent slots: SK(2t+1)=SK(2t)+1)
        int sk = SK(2 * t);
        s[sk]     = (c2.x >= 0.f) ? c2.x : 0.f;
        s[sk + 1] = (c2.y >= 0.f) ? c2.y : 0.f;
    }

    cnt = warpSum(cnt); dmz2 = warpSum(dmz2); di2 = warpSum(di2);
    spmz = warpSum(spmz); spint = warpSum(spint);
    mxm = warpMax(mxm); mxi = warpMax(mxi);
    if (lane == 0) {
        red7[0][w] = cnt; red7[1][w] = dmz2; red7[2][w] = di2;
        red7[3][w] = spmz; red7[4][w] = spint; red7[5][w] = mxm; red7[6][w] = mxi;
    }
    __syncthreads();
    if (t < 7) {
        float v = red7[t][0];
        if (t < 5) { for (int i = 1; i < 8; i++) v += red7[t][i]; }
        else       { for (int i = 1; i < 8; i++) v = fmaxf(v, red7[t][i]); }
        switch (t) {
            case 0: g_pcnt[blk] = v; break;
            case 1: g_pdmz[blk] = v; break;
            case 2: g_pdi [blk] = v; break;
            case 3: g_pspm[blk] = v; break;
            case 4: g_pspi[blk] = v; break;
            case 5: g_pmxm[blk] = v; break;
            case 6: g_pmxi[blk] = v; break;
        }
    }

    // Bitonic sort (pair enumeration: 256 threads = 256 productive pairs/pass).
    // Warp w's pairs for j<=32 touch only elements [64w, 64w+64); cross-warp
    // writes happen only at j>=64 -> full barrier at j>=32 (one level conservative).
    #pragma unroll
    for (int k = 2; k <= CHUNK; k <<= 1) {
        #pragma unroll
        for (int j = k >> 1; j > 0; j >>= 1) {
            if (j >= 32) __syncthreads(); else __syncwarp();
            int i  = ((t & ~(j - 1)) << 1) | (t & (j - 1));
            int ii = i + j;
            int ai = SK(i), aj = SK(ii);
            float va = s[ai], vb = s[aj];
            bool asc = (i & k) == 0;
            if ((va > vb) == asc) { s[ai] = vb; s[aj] = va; }
        }
    }
    __syncthreads();

    {   // publish sorted chunk
        float2 v;
        int sk = SK(2 * t);
        v.x = s[sk]; v.y = s[sk + 1];
        ((float2*)g_sorted)[segBase / 2 + t] = v;
    }
}

// ================= Kernel 2: nearest-neighbor soft intersect =================
__global__ __launch_bounds__(NTHR) void kSearch(const float* __restrict__ pred_mz,
                                                const float* __restrict__ pred_intensity) {
    __shared__ float s2[SKSZ];      // 4 skewed chunk regions (full batch row, sorted)
    __shared__ float redI[8];
    const int t    = threadIdx.x;
    const int lane = t & 31;
    const int w    = t >> 5;
    const int blk  = blockIdx.x;
    const int b    = blk >> 2;
    const int segBase = blk * CHUNK;

    // load all 4 sorted chunks of batch b into skewed regions
    #pragma unroll
    for (int rc = 0; rc < NCHUNK; rc++) {
        float2 v = ((const float2*)g_sorted)[(b * SEQ + rc * CHUNK) / 2 + t];
        int sk = REG * rc + SK(2 * t);
        s2[sk] = v.x; s2[sk + 1] = v.y;
    }
    const float2 a2 = ((const float2*)pred_mz)       [segBase / 2 + t];
    const float2 y2 = ((const float2*)pred_intensity)[segBase / 2 + t];
    __syncthreads();

    // max_j exp(-|a-mz_j|/T) = exp(-min_dist/T). 8 searches (2 queries x 4 chunks)
    // interleaved step-major: 8 independent LDS in flight per step (MLP=8).
    float acc = 0.f;
    {
        float av[2] = {a2.x, a2.y}, yv[2] = {y2.x, y2.y};
        int pos[2][NCHUNK] = {{0,0,0,0},{0,0,0,0}};
        #pragma unroll
        for (int st = CHUNK / 2; st > 0; st >>= 1) {
            #pragma unroll
            for (int q = 0; q < 2; q++) {
                #pragma unroll
                for (int rc = 0; rc < NCHUNK; rc++) {
                    if (s2[REG * rc + SK(pos[q][rc] + st - 1)] < av[q])
                        pos[q][rc] += st;              // pos <= 511 always
                }
            }
        }
        #pragma unroll
        for (int q = 0; q < 2; q++) {
            float a = av[q];
            float d = 3.0e38f;
            #pragma unroll
            for (int rc = 0; rc < NCHUNK; rc++) {
                int p = pos[q][rc];
                float hi = s2[REG * rc + SK(p)];
                float lo = s2[REG * rc + SK(p > 0 ? p - 1 : 0)];
                d = fminf(d, fabsf(a - hi));           // bracket covers pos==0 and
                d = fminf(d, fabsf(a - lo));           // saturated pos==511 via fabsf
            }
            float m = __expf(-10.0f * d) * yv[q];
            acc += (a >= 0.f) ? m : 0.f;               // masked query contributes 0
        }
    }
    acc = warpSum(acc);
    if (lane == 0) redI[w] = acc;
    __syncthreads();
    if (t == 0) {
        float v = redI[0];
        for (int i = 1; i < 8; i++) v += redI[i];
        g_pint[blk] = v;
    }
}

// ================= Kernel 3: finalize 4 scalars =================
__global__ void kFinal(float* __restrict__ out) {
    const int t = threadIdx.x;     // 32 threads, batch = t
    const float EPS = 1e-8f;
    float I = 0.f, U = 0.f, sdm = 0.f, sdi = 0.f, ssm = 0.f, ssi = 0.f;
    float mm = 0.f, mi = 0.f;
    #pragma unroll
    for (int cc = 0; cc < 4; cc++) {
        int idx = 4 * t + cc;
        I   += g_pint[idx];
        U   += g_pcnt[idx];
        sdm += g_pdmz[idx];
        sdi += g_pdi [idx];
        ssm += g_pspm[idx];
        ssi += g_pspi[idx];
        mm = fmaxf(mm, g_pmxm[idx]);
        mi = fmaxf(mi, g_pmxi[idx]);
    }
    float sj = 1.f - (I + EPS) / (U + EPS);
    sj  = warpSum(sj);
    sdm = warpSum(sdm); sdi = warpSum(sdi);
    ssm = warpSum(ssm); ssi = warpSum(ssi);
    mm  = warpMax(mm);  mi  = warpMax(mi);
    if (t == 0) {
        const float N = (float)(BATCH * SEQ);
        out[0] = sj / (float)BATCH;               // soft jaccard loss
        out[1] = (sdm / N) / (mm * mm);           // mse mz (normalized)
        out[2] = (sdi / N) / (mi * mi);           // mse intensity (normalized)
        out[3] = (ssm / N + ssi / N) * 0.5f;      // sign penalty
    }
}

extern "C" void kernel_launch(void* const* d_in, const int* in_sizes, int n_in,
                              void* d_out, int out_size) {
    const float* pred_mz        = (const float*)d_in[0];
    const float* mz             = (const float*)d_in[1];
    const float* intensity      = (const float*)d_in[2];
    const float* pred_intensity = (const float*)d_in[3];
    float* out = (float*)d_out;

    kSort  <<<NBLK, NTHR>>>(pred_mz, mz, intensity, pred_intensity);
    kSearch<<<NBLK, NTHR>>>(pred_mz, pred_intensity);
    kFinal <<<1, 32>>>(out);
}

// round 9
// speedup vs baseline: 2.1399x; 1.1905x over previous
#include <cuda_runtime.h>

#define BATCH  32
#define SEQ    2048
#define CHUNK  512
#define NCHUNK 4                  // SEQ / CHUNK
#define NBLK   (BATCH * NCHUNK)   // 128
#define NTHR   256

// ---- scratch (allocation-free: __device__ globals; all rewritten every run) ----
__device__ float g_sorted[BATCH * SEQ];
__device__ float g_pcnt[NBLK], g_pdmz[NBLK], g_pdi[NBLK], g_pspm[NBLK],
                 g_pspi[NBLK], g_pmxm[NBLK], g_pmxi[NBLK], g_pint[NBLK];

__device__ __forceinline__ int SK(int i) { return i + (i >> 5); }  // bank-skew index
#define REG   528                 // skewed size of one 512-chunk region
#define SKSZ  (NCHUNK * REG)      // 2112 floats

__device__ __forceinline__ float warpSum(float v) {
    #pragma unroll
    for (int o = 16; o; o >>= 1) v += __shfl_down_sync(0xffffffffu, v, o);
    return v;
}
__device__ __forceinline__ float warpMax(float v) {
    #pragma unroll
    for (int o = 16; o; o >>= 1) v = fmaxf(v, __shfl_down_sync(0xffffffffu, v, o));
    return v;
}

// Bitonic compare-exchange via shuffle (j < 32). Both partners execute; validity:
// j < k always, so asc = (idx & k)==0 is identical for both partners of a pair.
__device__ __forceinline__ void ceShfl(float& e, int idx, int k, int j) {
    float p = __shfl_xor_sync(0xffffffffu, e, j);
    bool lower = (idx & j) == 0;
    bool asc   = (idx & k) == 0;
    e = (lower == asc) ? fminf(e, p) : fmaxf(e, p);
}
// In-thread j==32 stage: e0 at idx0 (bit5 clear -> lower partner), e1 at idx0+32.
__device__ __forceinline__ void ceLocal(float& e0, float& e1, int idx0, int k) {
    bool asc = (idx0 & k) == 0;
    if ((e0 > e1) == asc) { float tmp = e0; e0 = e1; e1 = tmp; }
}
// Tail stages j=32..1 of merge step k, fully in registers.
__device__ __forceinline__ void warpTail(float& e0, float& e1, int idx0, int idx1, int k) {
    ceLocal(e0, e1, idx0, k);
    #pragma unroll
    for (int j = 16; j > 0; j >>= 1) { ceShfl(e0, idx0, k, j); ceShfl(e1, idx1, k, j); }
}

// ================= Kernel 1: stats partials + per-chunk bitonic sort =================
__global__ __launch_bounds__(NTHR) void kSort(const float* __restrict__ pred_mz,
                                              const float* __restrict__ mz,
                                              const float* __restrict__ intensity,
                                              const float* __restrict__ pred_intensity) {
    __shared__ float s[CHUNK];      // merge-stage staging (all accesses warp-coalesced)
    __shared__ float red7[7][8];
    const int t    = threadIdx.x;
    const int lane = t & 31;
    const int w    = t >> 5;
    const int blk  = blockIdx.x;
    const int segBase = blk * CHUNK;

    // Sort-layout element ownership: lane L of warp w owns idx0=64w+L, idx1=idx0+32.
    const int idx0 = 64 * w + lane;
    const int idx1 = idx0 + 32;
    const int g0 = segBase + idx0, g1 = segBase + idx1;

    const float a0 = pred_mz[g0],        a1 = pred_mz[g1];
    const float c0 = mz[g0],             c1 = mz[g1];
    const float x0 = intensity[g0],      x1 = intensity[g1];
    const float y0 = pred_intensity[g0], y1 = pred_intensity[g1];

    // ---- per-block stats partials ----
    float cnt = 0.f, dmz2 = 0.f, di2 = 0.f, spmz = 0.f, spint = 0.f, mxm = 0.f, mxi = 0.f;
    {
        float av[2] = {a0, a1}, cv[2] = {c0, c1}, xv[2] = {x0, x1}, yv[2] = {y0, y1};
        #pragma unroll
        for (int r = 0; r < 2; r++) {
            float a = av[r], cc = cv[r], x = xv[r], y = yv[r];
            cnt += (a >= 0.f ? 1.f : 0.f) + (cc >= 0.f ? 1.f : 0.f);
            float d1 = a - cc; dmz2 += d1 * d1;
            float d2 = y - x;  di2  += d2 * d2;
            float sa = (float)((a  > 0.f) - (a  < 0.f));
            float sc = (float)((cc > 0.f) - (cc < 0.f));
            float sx = (float)((x  > 0.f) - (x  < 0.f));
            float sy = (float)((y  > 0.f) - (y  < 0.f));
            spmz  += fabsf(sa - sc);
            spint += fabsf(sy - sx);
            mxm = fmaxf(mxm, fabsf(cc));
            mxi = fmaxf(mxi, fabsf(x));
        }
    }
    cnt = warpSum(cnt); dmz2 = warpSum(dmz2); di2 = warpSum(di2);
    spmz = warpSum(spmz); spint = warpSum(spint);
    mxm = warpMax(mxm); mxi = warpMax(mxi);
    if (lane == 0) {
        red7[0][w] = cnt; red7[1][w] = dmz2; red7[2][w] = di2;
        red7[3][w] = spmz; red7[4][w] = spint; red7[5][w] = mxm; red7[6][w] = mxi;
    }

    // ---- warp-register bitonic sort of each 64-run (k=2..64): zero block barriers ----
    float e0 = (c0 >= 0.f) ? c0 : 0.f;     // masked mz
    float e1 = (c1 >= 0.f) ? c1 : 0.f;
    #pragma unroll
    for (int k = 2; k <= 64; k <<= 1) {
        #pragma unroll
        for (int j = k >> 1; j > 0; j >>= 1) {
            if (j == 32) ceLocal(e0, e1, idx0, k);
            else         { ceShfl(e0, idx0, k, j); ceShfl(e1, idx1, k, j); }
        }
    }

    // reduce stats while sort results settle (uses red7 written before any barrier)
    __syncthreads();
    if (t < 7) {
        float v = red7[t][0];
        if (t < 5) { for (int i = 1; i < 8; i++) v += red7[t][i]; }
        else       { for (int i = 1; i < 8; i++) v = fmaxf(v, red7[t][i]); }
        switch (t) {
            case 0: g_pcnt[blk] = v; break;
            case 1: g_pdmz[blk] = v; break;
            case 2: g_pdi [blk] = v; break;
            case 3: g_pspm[blk] = v; break;
            case 4: g_pspi[blk] = v; break;
            case 5: g_pmxm[blk] = v; break;
            case 6: g_pmxi[blk] = v; break;
        }
    }

    // ---- merge stages k=128,256,512: only j>=64 passes touch smem ----
    s[idx0] = e0; s[idx1] = e1;
    __syncthreads();

    #pragma unroll
    for (int k = 128; k <= CHUNK; k <<= 1) {
        // smem passes j = k/2 .. 64 (pair enumeration; warp-coalesced accesses)
        #pragma unroll
        for (int j = k >> 1; j >= 64; j >>= 1) {
            int i  = ((t & ~(j - 1)) << 1) | (t & (j - 1));
            int ii = i + j;
            float va = s[i], vb = s[ii];
            bool asc = (i & k) == 0;
            if ((va > vb) == asc) { s[i] = vb; s[ii] = va; }
            __syncthreads();
        }
        // register tail j=32..1
        e0 = s[idx0]; e1 = s[idx1];
        warpTail(e0, e1, idx0, idx1, k);
        if (k < CHUNK) {
            s[idx0] = e0; s[idx1] = e1;
            __syncthreads();
        }
    }

    // final sorted values live in registers -> publish directly (coalesced per warp)
    g_sorted[segBase + idx0] = e0;
    g_sorted[segBase + idx1] = e1;
}

// ================= Kernel 2: nearest-neighbor soft intersect =================
__global__ __launch_bounds__(NTHR) void kSearch(const float* __restrict__ pred_mz,
                                                const float* __restrict__ pred_intensity) {
    __shared__ float s2[SKSZ];      // 4 skewed chunk regions (full batch row, sorted)
    __shared__ float redI[8];
    const int t    = threadIdx.x;
    const int lane = t & 31;
    const int w    = t >> 5;
    const int blk  = blockIdx.x;
    const int b    = blk >> 2;
    const int segBase = blk * CHUNK;

    // load all 4 sorted chunks of batch b into skewed regions
    #pragma unroll
    for (int rc = 0; rc < NCHUNK; rc++) {
        float2 v = ((const float2*)g_sorted)[(b * SEQ + rc * CHUNK) / 2 + t];
        int sk = REG * rc + SK(2 * t);
        s2[sk] = v.x; s2[sk + 1] = v.y;
    }
    const float2 a2 = ((const float2*)pred_mz)       [segBase / 2 + t];
    const float2 y2 = ((const float2*)pred_intensity)[segBase / 2 + t];
    __syncthreads();

    // max_j exp(-|a-mz_j|/T) = exp(-min_dist/T). 8 searches (2 queries x 4 chunks)
    // interleaved step-major: 8 independent LDS in flight per step (MLP=8).
    float acc = 0.f;
    {
        float av[2] = {a2.x, a2.y}, yv[2] = {y2.x, y2.y};
        int pos[2][NCHUNK] = {{0,0,0,0},{0,0,0,0}};
        #pragma unroll
        for (int st = CHUNK / 2; st > 0; st >>= 1) {
            #pragma unroll
            for (int q = 0; q < 2; q++) {
                #pragma unroll
                for (int rc = 0; rc < NCHUNK; rc++) {
                    if (s2[REG * rc + SK(pos[q][rc] + st - 1)] < av[q])
                        pos[q][rc] += st;              // pos <= 511 always
                }
            }
        }
        #pragma unroll
        for (int q = 0; q < 2; q++) {
            float a = av[q];
            float d = 3.0e38f;
            #pragma unroll
            for (int rc = 0; rc < NCHUNK; rc++) {
                int p = pos[q][rc];
                float hi = s2[REG * rc + SK(p)];
                float lo = s2[REG * rc + SK(p > 0 ? p - 1 : 0)];
                d = fminf(d, fabsf(a - hi));           // bracket covers pos==0 and
                d = fminf(d, fabsf(a - lo));           // saturated pos==511 via fabsf
            }
            float m = __expf(-10.0f * d) * yv[q];
            acc += (a >= 0.f) ? m : 0.f;               // masked query contributes 0
        }
    }
    acc = warpSum(acc);
    if (lane == 0) redI[w] = acc;
    __syncthreads();
    if (t == 0) {
        float v = redI[0];
        for (int i = 1; i < 8; i++) v += redI[i];
        g_pint[blk] = v;
    }
}

// ================= Kernel 3: finalize 4 scalars =================
__global__ void kFinal(float* __restrict__ out) {
    const int t = threadIdx.x;     // 32 threads, batch = t
    const float EPS = 1e-8f;
    float I = 0.f, U = 0.f, sdm = 0.f, sdi = 0.f, ssm = 0.f, ssi = 0.f;
    float mm = 0.f, mi = 0.f;
    #pragma unroll
    for (int cc = 0; cc < 4; cc++) {
        int idx = 4 * t + cc;
        I   += g_pint[idx];
        U   += g_pcnt[idx];
        sdm += g_pdmz[idx];
        sdi += g_pdi [idx];
        ssm += g_pspm[idx];
        ssi += g_pspi[idx];
        mm = fmaxf(mm, g_pmxm[idx]);
        mi = fmaxf(mi, g_pmxi[idx]);
    }
    float sj = 1.f - (I + EPS) / (U + EPS);
    sj  = warpSum(sj);
    sdm = warpSum(sdm); sdi = warpSum(sdi);
    ssm = warpSum(ssm); ssi = warpSum(ssi);
    mm  = warpMax(mm);  mi  = warpMax(mi);
    if (t == 0) {
        const float N = (float)(BATCH * SEQ);
        out[0] = sj / (float)BATCH;               // soft jaccard loss
        out[1] = (sdm / N) / (mm * mm);           // mse mz (normalized)
        out[2] = (sdi / N) / (mi * mi);           // mse intensity (normalized)
        out[3] = (ssm / N + ssi / N) * 0.5f;      // sign penalty
    }
}

extern "C" void kernel_launch(void* const* d_in, const int* in_sizes, int n_in,
                              void* d_out, int out_size) {
    const float* pred_mz        = (const float*)d_in[0];
    const float* mz             = (const float*)d_in[1];
    const float* intensity      = (const float*)d_in[2];
    const float* pred_intensity = (const float*)d_in[3];
    float* out = (float*)d_out;

    kSort  <<<NBLK, NTHR>>>(pred_mz, mz, intensity, pred_intensity);
    kSearch<<<NBLK, NTHR>>>(pred_mz, pred_intensity);
    kFinal <<<1, 32>>>(out);
}